// round 15
// baseline (speedup 1.0000x reference)
#include <cuda_runtime.h>

constexpr int Bc = 512;
constexpr int Lc = 200;
constexpr int Ec = 64;

// ---------------- smem layout (floats) ----------------
constexpr int WTP    = 68;                        // wT[48][68]: wT[c][j]
constexpr int WT_OFF = 0;
constexpr int XSS    = 68;                        // xs[128][68] row-major
constexpr int XS_OFF = WT_OFF + 48 * WTP;         // 3264
constexpr int KTS    = 208;                       // kt[16][208]: kt[d][t]
constexpr int KT_OFF = XS_OFF + 128 * XSS;        // 11968
constexpr int QS_OFF = KT_OFF + 16 * KTS;         // q[200][16] (pre-scaled by 0.25*log2e)
constexpr int VS_OFF = QS_OFF + Lc * 16;          // v[200][16]
constexpr int WC_OFF = VS_OFF + Lc * 16;          // col sums [200]
constexpr int SP_OFF = WC_OFF + Lc + 8;           // partials [16][16]
constexpr int SM1_F  = SP_OFF + 256;              // 22160 floats = 88640 B

__device__ int g_len[Bc];
__device__ int g_order[Bc];

__device__ __forceinline__ float ex2f(float x) {
    float y;
    asm("ex2.approx.ftz.f32 %0, %1;" : "=f"(y) : "f"(x));
    return y;
}

// ---- fused pre-kernel: per-batch length + counting sort (descending) ----
__global__ void __launch_bounds__(512) sort_kernel(const int* __restrict__ mask) {
    __shared__ int hist[Lc + 1];
    __shared__ int offs[Lc + 1];
    const int tid = threadIdx.x;      // == batch id (512 threads)

    int len = 0;
    const int4* m4 = (const int4*)(mask + (size_t)tid * Lc);
#pragma unroll
    for (int i = 0; i < Lc / 4; i++) {
        int4 v = m4[i];
        len += (v.x != 0) + (v.y != 0) + (v.z != 0) + (v.w != 0);
    }
    g_len[tid] = len;

    for (int i = tid; i <= Lc; i += 512) hist[i] = 0;
    __syncthreads();
    atomicAdd(&hist[len], 1);
    __syncthreads();
    if (tid == 0) {
        int acc = 0;
        for (int l = Lc; l >= 0; l--) { offs[l] = acc; acc += hist[l]; }
    }
    __syncthreads();
    int pos = atomicAdd(&offs[len], 1);
    g_order[pos] = tid;
}

extern __shared__ float sw[];

// phase-1 tile body: NR rows per thread (rows rowgrp + 32*rr), 6 cols
template <int NR>
__device__ __forceinline__ void proj_tile(int rowgrp, int colgrp, int tb, int len,
                                          const float* bias, float QSC) {
    float acc[NR][6];
#pragma unroll
    for (int rr = 0; rr < NR; rr++)
#pragma unroll
        for (int s = 0; s < 6; s++) acc[rr][s] = 0.f;

#pragma unroll
    for (int j4 = 0; j4 < 64; j4 += 4) {
        float4 xv[NR];
#pragma unroll
        for (int rr = 0; rr < NR; rr++)
            xv[rr] = *(const float4*)(sw + XS_OFF + (rowgrp + 32 * rr) * XSS + j4);
#pragma unroll
        for (int s = 0; s < 6; s++) {
            float4 wq = *(const float4*)(sw + WT_OFF + (colgrp + 8 * s) * WTP + j4);
#pragma unroll
            for (int rr = 0; rr < NR; rr++) {
                acc[rr][s] = fmaf(xv[rr].x, wq.x, acc[rr][s]);
                acc[rr][s] = fmaf(xv[rr].y, wq.y, acc[rr][s]);
                acc[rr][s] = fmaf(xv[rr].z, wq.z, acc[rr][s]);
                acc[rr][s] = fmaf(xv[rr].w, wq.w, acc[rr][s]);
            }
        }
    }

#pragma unroll
    for (int rr = 0; rr < NR; rr++) {
        int t = tb + rowgrp + 32 * rr;
        if (t < len) {
#pragma unroll
            for (int s = 0; s < 6; s++) {
                int c = colgrp + 8 * s;
                float v = acc[rr][s] + bias[s];
                if (c < 16)       sw[KT_OFF + c * KTS + t] = v;
                else if (c < 32)  sw[VS_OFF + t * 16 + (c - 16)] = v;
                else              sw[QS_OFF + t * 16 + (c - 32)] = v * QSC;
            }
        }
    }
}

__global__ void __launch_bounds__(256, 2)
attn_head_kernel(const float* __restrict__ input,
                 const float* __restrict__ pos_enc,
                 const float* __restrict__ Wk, const float* __restrict__ bk,
                 const float* __restrict__ Wv, const float* __restrict__ bv,
                 const float* __restrict__ Wq, const float* __restrict__ bq,
                 const float* __restrict__ Wf, const float* __restrict__ bf,
                 float* __restrict__ out) {
    const int tid  = threadIdx.x;
    const int lane = tid & 31;
    const int wid  = tid >> 5;
    const int b    = g_order[blockIdx.x >> 2];   // longest-first schedule
    const int h    = blockIdx.x & 3;
    const int len  = g_len[b];

    // ---- phase 0: weights transposed: wT[c][j], c = m*16+i ----
    for (int idx = tid; idx < 64 * 48; idx += 256) {
        int c = idx >> 6, j = idx & 63;
        int m = c >> 4, i = c & 15;
        const float* Wm = (m == 0) ? Wk : ((m == 1) ? Wv : Wq);
        sw[WT_OFF + c * WTP + j] = Wm[(h * 16 + i) * 64 + j];
    }
    if (tid < Lc) sw[WC_OFF + tid] = 0.0f;
    __syncthreads();

    // ---- phase 1: register-tiled GEMM, len-adaptive row count ----
    const int rowgrp = tid >> 3;          // 0..31
    const int colgrp = tid & 7;           // 0..7
    const float QSC = 0.36067376022224085f;   // 0.25 * log2(e)

    float bias[6];
#pragma unroll
    for (int s = 0; s < 6; s++) {
        int c = colgrp + 8 * s, m = c >> 4, i = c & 15;
        bias[s] = (m == 0) ? bk[h * 16 + i] : ((m == 1) ? bv[h * 16 + i] : bq[h * 16 + i]);
    }

    const int ntiles = (len + 127) >> 7;
    for (int tile = 0; tile < ntiles; tile++) {
        const int tb = tile * 128;
        int R = len - tb; if (R > 128) R = 128;
        const int fmax = R << 4;
        const float4* in4 = (const float4*)(input + ((size_t)b * Lc + tb) * Ec);
        const float4* pe4 = (const float4*)(pos_enc + (size_t)tb * Ec);
#pragma unroll
        for (int v = 0; v < 8; v++) {
            int f = tid + v * 256;
            if (f < fmax) {
                int t = f >> 4, e0 = (f & 15) * 4;
                float4 a = in4[f], p = pe4[f];
                *(float4*)(sw + XS_OFF + t * XSS + e0) =
                    make_float4(a.x + p.x, a.y + p.y, a.z + p.z, a.w + p.w);
            }
        }
        __syncthreads();

        if (rowgrp < R) {
            const int nr = (R + 31) >> 5;
            switch (nr) {
                case 1: proj_tile<1>(rowgrp, colgrp, tb, len, bias, QSC); break;
                case 2: proj_tile<2>(rowgrp, colgrp, tb, len, bias, QSC); break;
                case 3: proj_tile<3>(rowgrp, colgrp, tb, len, bias, QSC); break;
                default: proj_tile<4>(rowgrp, colgrp, tb, len, bias, QSC); break;
            }
        }
        __syncthreads();
    }

    // ---- phase 2: scores + softmax + column sums ----
    // full 64-key blocks (unguarded) + tail: 64-guarded (rem>32) or 32-key path (rem<=32)
    const int nbf = len >> 6;            // 0..3 full blocks
    const int rem = len & 63;            // 0..63
    const bool t64 = rem > 32;

    float wacc[4][2];
#pragma unroll
    for (int kb = 0; kb < 4; kb++) { wacc[kb][0] = 0.f; wacc[kb][1] = 0.f; }

    for (int qb = wid * 4; qb < len; qb += 32) {
        float qv[4][16];
#pragma unroll
        for (int qq = 0; qq < 4; qq++) {
            int q = qb + qq; q = (q < len) ? q : 0;
            const float4* p = (const float4*)(sw + QS_OFF + q * 16);
#pragma unroll
            for (int jj = 0; jj < 4; jj++) {
                float4 v = p[jj];
                qv[qq][4 * jj + 0] = v.x; qv[qq][4 * jj + 1] = v.y;
                qv[qq][4 * jj + 2] = v.z; qv[qq][4 * jj + 3] = v.w;
            }
        }

        float ee[4][4][2];
        float z[4] = {0.f, 0.f, 0.f, 0.f};
#pragma unroll
        for (int kb = 0; kb < 4; kb++) {
            if (kb < nbf) {
                // full block: every key valid, no guards
                const float* kp = sw + KT_OFF + kb * 64 + lane * 2;
                float a0[4], a1[4];
#pragma unroll
                for (int qq = 0; qq < 4; qq++) { a0[qq] = 0.f; a1[qq] = 0.f; }
#pragma unroll
                for (int j = 0; j < 16; j++) {
                    float2 kt2 = *(const float2*)(kp + j * KTS);
#pragma unroll
                    for (int qq = 0; qq < 4; qq++) {
                        a0[qq] = fmaf(kt2.x, qv[qq][j], a0[qq]);
                        a1[qq] = fmaf(kt2.y, qv[qq][j], a1[qq]);
                    }
                }
#pragma unroll
                for (int qq = 0; qq < 4; qq++) {
                    float e0 = ex2f(a0[qq]);
                    float e1 = ex2f(a1[qq]);
                    ee[kb][qq][0] = e0; ee[kb][qq][1] = e1;
                    z[qq] += e0 + e1;
                }
            } else if (kb == nbf && rem) {
                if (t64) {
                    const int k0 = kb * 64 + lane * 2;
                    const float* kp = sw + KT_OFF + k0;
                    float a0[4], a1[4];
#pragma unroll
                    for (int qq = 0; qq < 4; qq++) { a0[qq] = 0.f; a1[qq] = 0.f; }
#pragma unroll
                    for (int j = 0; j < 16; j++) {
                        float2 kt2 = *(const float2*)(kp + j * KTS);
#pragma unroll
                        for (int qq = 0; qq < 4; qq++) {
                            a0[qq] = fmaf(kt2.x, qv[qq][j], a0[qq]);
                            a1[qq] = fmaf(kt2.y, qv[qq][j], a1[qq]);
                        }
                    }
                    const bool ok0 = (k0 + 0) < len;
                    const bool ok1 = (k0 + 1) < len;
#pragma unroll
                    for (int qq = 0; qq < 4; qq++) {
                        float e0 = ok0 ? ex2f(a0[qq]) : 0.f;
                        float e1 = ok1 ? ex2f(a1[qq]) : 0.f;
                        ee[kb][qq][0] = e0; ee[kb][qq][1] = e1;
                        z[qq] += e0 + e1;
                    }
                } else {
                    // 32-key tail: lane owns 1 key
                    const int k0 = kb * 64 + lane;
                    const float* kp = sw + KT_OFF + k0;
                    float a0[4];
#pragma unroll
                    for (int qq = 0; qq < 4; qq++) a0[qq] = 0.f;
#pragma unroll
                    for (int j = 0; j < 16; j++) {
                        float kt = kp[j * KTS];
#pragma unroll
                        for (int qq = 0; qq < 4; qq++)
                            a0[qq] = fmaf(kt, qv[qq][j], a0[qq]);
                    }
                    const bool ok = lane < rem;
#pragma unroll
                    for (int qq = 0; qq < 4; qq++) {
                        float e0 = ok ? ex2f(a0[qq]) : 0.f;
                        ee[kb][qq][0] = e0; ee[kb][qq][1] = 0.f;
                        z[qq] += e0;
                    }
                }
            } else {
#pragma unroll
                for (int qq = 0; qq < 4; qq++) { ee[kb][qq][0] = 0.f; ee[kb][qq][1] = 0.f; }
            }
        }

#pragma unroll
        for (int o = 16; o; o >>= 1) {
            z[0] += __shfl_xor_sync(0xffffffffu, z[0], o);
            z[1] += __shfl_xor_sync(0xffffffffu, z[1], o);
            z[2] += __shfl_xor_sync(0xffffffffu, z[2], o);
            z[3] += __shfl_xor_sync(0xffffffffu, z[3], o);
        }
        float inv[4];
#pragma unroll
        for (int qq = 0; qq < 4; qq++)
            inv[qq] = (qb + qq < len) ? __fdividef(1.0f, z[qq]) : 0.0f;
#pragma unroll
        for (int kb = 0; kb < 4; kb++) {
            if (kb < nbf || (kb == nbf && rem)) {
#pragma unroll
                for (int qq = 0; qq < 4; qq++) {
                    wacc[kb][0] = fmaf(ee[kb][qq][0], inv[qq], wacc[kb][0]);
                    wacc[kb][1] = fmaf(ee[kb][qq][1], inv[qq], wacc[kb][1]);
                }
            }
        }
    }

#pragma unroll
    for (int kb = 0; kb < 4; kb++) {
        if (kb < nbf) {
            int k = kb * 64 + lane * 2;
            atomicAdd(&sw[WC_OFF + k],     wacc[kb][0]);
            atomicAdd(&sw[WC_OFF + k + 1], wacc[kb][1]);
        } else if (kb == nbf && rem) {
            if (t64) {
                int k = kb * 64 + lane * 2;
                if (k < len)     atomicAdd(&sw[WC_OFF + k],     wacc[kb][0]);
                if (k + 1 < len) atomicAdd(&sw[WC_OFF + k + 1], wacc[kb][1]);
            } else {
                int k = kb * 64 + lane;
                if (lane < rem) atomicAdd(&sw[WC_OFF + k], wacc[kb][0]);
            }
        }
    }
    __syncthreads();

    // ---- phase 3: S[c] = sum_k wc[k] * V[k][c] ----
    {
        const int c = tid & 15, part = tid >> 4;
        float acc = 0.f;
        for (int k = part; k < len; k += 16)
            acc = fmaf(sw[WC_OFF + k], sw[VS_OFF + k * 16 + c], acc);
        sw[SP_OFF + part * 16 + c] = acc;
    }
    __syncthreads();
    if (tid < 16) {
        float s = 0.f;
#pragma unroll
        for (int p = 0; p < 16; p++) s += sw[SP_OFF + p * 16 + tid];
        sw[SP_OFF + tid] = s;
    }
    __syncthreads();

    // ---- phase 4 (fused): out[b][e] += inv*(S_head . Wf[e, h*16:]) (+ bf on h==0) ----
    if (tid < 64) {
        float acc = 0.f;
        const float* wfr = Wf + tid * 64 + h * 16;
#pragma unroll
        for (int i = 0; i < 16; i++)
            acc = fmaf(sw[SP_OFF + i], wfr[i], acc);
        const float lenf = (float)len;
        const float invd = 1.0f / (lenf + 1e-8f);
        float val = acc * invd;
        if (h == 0) val = fmaf(bf[tid], lenf * invd, val);
        atomicAdd(out + b * 64 + tid, val);
    }
}

extern "C" void kernel_launch(void* const* d_in, const int* in_sizes, int n_in,
                              void* d_out, int out_size) {
    const float* input   = (const float*)d_in[0];
    const int*   mask    = (const int*)d_in[1];
    const float* pos_enc = (const float*)d_in[2];
    const float* Wk      = (const float*)d_in[3];
    const float* bk      = (const float*)d_in[4];
    const float* Wv      = (const float*)d_in[5];
    const float* bv      = (const float*)d_in[6];
    const float* Wq      = (const float*)d_in[7];
    const float* bq      = (const float*)d_in[8];
    const float* Wf      = (const float*)d_in[9];
    const float* bf      = (const float*)d_in[10];
    float* out           = (float*)d_out;

    cudaMemsetAsync(out, 0, (size_t)Bc * Ec * sizeof(float), 0);
    sort_kernel<<<1, 512>>>(mask);

    const size_t smem1 = (size_t)SM1_F * sizeof(float);
    cudaFuncSetAttribute(attn_head_kernel,
                         cudaFuncAttributeMaxDynamicSharedMemorySize, (int)smem1);
    attn_head_kernel<<<Bc * 4, 256, smem1>>>(input, pos_enc,
                                             Wk, bk, Wv, bv, Wq, bq, Wf, bf, out);
}

// round 16
// speedup vs baseline: 1.0347x; 1.0347x over previous
#include <cuda_runtime.h>

constexpr int Bc = 512;
constexpr int Lc = 200;
constexpr int Ec = 64;

// ---------------- smem layout (floats) ----------------
constexpr int WTP    = 68;                        // wT[48][68]: wT[c][j]
constexpr int WT_OFF = 0;
constexpr int XSS    = 68;                        // xs[128][68] row-major
constexpr int XS_OFF = WT_OFF + 48 * WTP;         // 3264
constexpr int KTS    = 208;                       // kt[16][208]: kt[d][t]
constexpr int KT_OFF = XS_OFF + 128 * XSS;        // 11968
constexpr int QS_OFF = KT_OFF + 16 * KTS;         // q[200][16] (pre-scaled by 0.25*log2e)
constexpr int VS_OFF = QS_OFF + Lc * 16;          // v[200][16]
constexpr int WC_OFF = VS_OFF + Lc * 16;          // col sums [200]
constexpr int SP_OFF = WC_OFF + Lc + 8;           // partials [16][16]
constexpr int SM1_F  = SP_OFF + 256;              // 22160 floats = 88640 B

__device__ int g_len[Bc];
__device__ int g_order[Bc];

__device__ __forceinline__ float ex2f(float x) {
    float y;
    asm("ex2.approx.ftz.f32 %0, %1;" : "=f"(y) : "f"(x));
    return y;
}

// ---- pre-kernel 1: per-batch valid length + zero this batch's output slice ----
__global__ void len_kernel(const int* __restrict__ mask, float* __restrict__ out) {
    int b = blockIdx.x;
    int pred = (threadIdx.x < Lc) && (mask[(size_t)b * Lc + threadIdx.x] != 0);
    int len = __syncthreads_count(pred);
    if (threadIdx.x == 0) g_len[b] = len;
    if (threadIdx.x < Ec) out[b * Ec + threadIdx.x] = 0.0f;
}

// ---- pre-kernel 2: counting sort, descending len ----
__global__ void sort_kernel() {
    __shared__ int hist[Lc + 1];
    __shared__ int offs[Lc + 1];
    const int tid = threadIdx.x;
    for (int i = tid; i <= Lc; i += 256) hist[i] = 0;
    __syncthreads();
    for (int b = tid; b < Bc; b += 256) atomicAdd(&hist[g_len[b]], 1);
    __syncthreads();
    if (tid == 0) {
        int acc = 0;
        for (int l = Lc; l >= 0; l--) { offs[l] = acc; acc += hist[l]; }
    }
    __syncthreads();
    for (int b = tid; b < Bc; b += 256) {
        int pos = atomicAdd(&offs[g_len[b]], 1);
        g_order[pos] = b;
    }
}

extern __shared__ float sw[];

// phase-1 tile body: NR rows per thread (rows rowgrp + 32*rr), 6 cols
template <int NR>
__device__ __forceinline__ void proj_tile(int rowgrp, int colgrp, int tb, int len,
                                          const float* bias, float QSC) {
    float acc[NR][6];
#pragma unroll
    for (int rr = 0; rr < NR; rr++)
#pragma unroll
        for (int s = 0; s < 6; s++) acc[rr][s] = 0.f;

#pragma unroll
    for (int j4 = 0; j4 < 64; j4 += 4) {
        float4 xv[NR];
#pragma unroll
        for (int rr = 0; rr < NR; rr++)
            xv[rr] = *(const float4*)(sw + XS_OFF + (rowgrp + 32 * rr) * XSS + j4);
#pragma unroll
        for (int s = 0; s < 6; s++) {
            float4 wq = *(const float4*)(sw + WT_OFF + (colgrp + 8 * s) * WTP + j4);
#pragma unroll
            for (int rr = 0; rr < NR; rr++) {
                acc[rr][s] = fmaf(xv[rr].x, wq.x, acc[rr][s]);
                acc[rr][s] = fmaf(xv[rr].y, wq.y, acc[rr][s]);
                acc[rr][s] = fmaf(xv[rr].z, wq.z, acc[rr][s]);
                acc[rr][s] = fmaf(xv[rr].w, wq.w, acc[rr][s]);
            }
        }
    }

#pragma unroll
    for (int rr = 0; rr < NR; rr++) {
        int t = tb + rowgrp + 32 * rr;
        if (t < len) {
#pragma unroll
            for (int s = 0; s < 6; s++) {
                int c = colgrp + 8 * s;
                float v = acc[rr][s] + bias[s];
                if (c < 16)       sw[KT_OFF + c * KTS + t] = v;
                else if (c < 32)  sw[VS_OFF + t * 16 + (c - 16)] = v;
                else              sw[QS_OFF + t * 16 + (c - 32)] = v * QSC;
            }
        }
    }
}

__global__ void __launch_bounds__(256, 2)
attn_head_kernel(const float* __restrict__ input,
                 const float* __restrict__ pos_enc,
                 const float* __restrict__ Wk, const float* __restrict__ bk,
                 const float* __restrict__ Wv, const float* __restrict__ bv,
                 const float* __restrict__ Wq, const float* __restrict__ bq,
                 const float* __restrict__ Wf, const float* __restrict__ bf,
                 float* __restrict__ out) {
    const int tid  = threadIdx.x;
    const int lane = tid & 31;
    const int wid  = tid >> 5;
    const int b    = g_order[blockIdx.x >> 2];   // longest-first schedule
    const int h    = blockIdx.x & 3;
    const int len  = g_len[b];

    // ---- phase 0: weights transposed: wT[c][j], c = m*16+i ----
    for (int idx = tid; idx < 64 * 48; idx += 256) {
        int c = idx >> 6, j = idx & 63;
        int m = c >> 4, i = c & 15;
        const float* Wm = (m == 0) ? Wk : ((m == 1) ? Wv : Wq);
        sw[WT_OFF + c * WTP + j] = Wm[(h * 16 + i) * 64 + j];
    }
    if (tid < Lc) sw[WC_OFF + tid] = 0.0f;
    __syncthreads();

    // ---- phase 1: register-tiled GEMM, len-adaptive row count ----
    const int rowgrp = tid >> 3;          // 0..31
    const int colgrp = tid & 7;           // 0..7
    const float QSC = 0.36067376022224085f;   // 0.25 * log2(e)

    float bias[6];
#pragma unroll
    for (int s = 0; s < 6; s++) {
        int c = colgrp + 8 * s, m = c >> 4, i = c & 15;
        bias[s] = (m == 0) ? bk[h * 16 + i] : ((m == 1) ? bv[h * 16 + i] : bq[h * 16 + i]);
    }

    const int ntiles = (len + 127) >> 7;
    for (int tile = 0; tile < ntiles; tile++) {
        const int tb = tile * 128;
        int R = len - tb; if (R > 128) R = 128;
        const int fmax = R << 4;
        const float4* in4 = (const float4*)(input + ((size_t)b * Lc + tb) * Ec);
        const float4* pe4 = (const float4*)(pos_enc + (size_t)tb * Ec);
#pragma unroll
        for (int v = 0; v < 8; v++) {
            int f = tid + v * 256;
            if (f < fmax) {
                int t = f >> 4, e0 = (f & 15) * 4;
                float4 a = in4[f], p = pe4[f];
                *(float4*)(sw + XS_OFF + t * XSS + e0) =
                    make_float4(a.x + p.x, a.y + p.y, a.z + p.z, a.w + p.w);
            }
        }
        __syncthreads();

        if (rowgrp < R) {
            const int nr = (R + 31) >> 5;
            switch (nr) {
                case 1: proj_tile<1>(rowgrp, colgrp, tb, len, bias, QSC); break;
                case 2: proj_tile<2>(rowgrp, colgrp, tb, len, bias, QSC); break;
                case 3: proj_tile<3>(rowgrp, colgrp, tb, len, bias, QSC); break;
                default: proj_tile<4>(rowgrp, colgrp, tb, len, bias, QSC); break;
            }
        }
        __syncthreads();
    }

    // ---- phase 2: scores + softmax + column sums ----
    // 6 query rows per warp iteration (quartered-D register discipline);
    // lane owns keys k = kb*64 + lane*2 + {0,1}
    const int nb = (len + 63) >> 6;              // 1..4 k-blocks of 64
    float wacc[4][2];
#pragma unroll
    for (int kb = 0; kb < 4; kb++) { wacc[kb][0] = 0.f; wacc[kb][1] = 0.f; }

    for (int qb = wid * 6; qb < len; qb += 48) {
        float a[4][6][2];                         // [kb][q][key] persistent
#pragma unroll
        for (int kb = 0; kb < 4; kb++)
#pragma unroll
            for (int qq = 0; qq < 6; qq++) { a[kb][qq][0] = 0.f; a[kb][qq][1] = 0.f; }

#pragma unroll
        for (int qt = 0; qt < 4; qt++) {          // quarter of D
            float qv[6][4];
#pragma unroll
            for (int qq = 0; qq < 6; qq++) {
                int q = qb + qq; q = (q < len) ? q : 0;
                float4 v = *(const float4*)(sw + QS_OFF + q * 16 + qt * 4);
                qv[qq][0] = v.x; qv[qq][1] = v.y; qv[qq][2] = v.z; qv[qq][3] = v.w;
            }
#pragma unroll
            for (int kb = 0; kb < 4; kb++) {
                if (kb < nb) {
                    const float* kp = sw + KT_OFF + (qt * 4) * KTS + kb * 64 + lane * 2;
#pragma unroll
                    for (int j = 0; j < 4; j++) {
                        float2 kt2 = *(const float2*)(kp + j * KTS);
#pragma unroll
                        for (int qq = 0; qq < 6; qq++) {
                            a[kb][qq][0] = fmaf(kt2.x, qv[qq][j], a[kb][qq][0]);
                            a[kb][qq][1] = fmaf(kt2.y, qv[qq][j], a[kb][qq][1]);
                        }
                    }
                }
            }
        }

        float z[6];
#pragma unroll
        for (int qq = 0; qq < 6; qq++) z[qq] = 0.f;
#pragma unroll
        for (int kb = 0; kb < 4; kb++) {
            if (kb < nb) {
                const int k0 = kb * 64 + lane * 2;
                const bool ok0 = (k0 + 0) < len;
                const bool ok1 = (k0 + 1) < len;
#pragma unroll
                for (int qq = 0; qq < 6; qq++) {
                    float e0 = ok0 ? ex2f(a[kb][qq][0]) : 0.f;
                    float e1 = ok1 ? ex2f(a[kb][qq][1]) : 0.f;
                    a[kb][qq][0] = e0; a[kb][qq][1] = e1;
                    z[qq] += e0 + e1;
                }
            }
        }

#pragma unroll
        for (int o = 16; o; o >>= 1) {
#pragma unroll
            for (int qq = 0; qq < 6; qq++)
                z[qq] += __shfl_xor_sync(0xffffffffu, z[qq], o);
        }
        float inv[6];
#pragma unroll
        for (int qq = 0; qq < 6; qq++)
            inv[qq] = (qb + qq < len) ? __fdividef(1.0f, z[qq]) : 0.0f;
#pragma unroll
        for (int kb = 0; kb < 4; kb++) {
            if (kb < nb) {
#pragma unroll
                for (int qq = 0; qq < 6; qq++) {
                    wacc[kb][0] = fmaf(a[kb][qq][0], inv[qq], wacc[kb][0]);
                    wacc[kb][1] = fmaf(a[kb][qq][1], inv[qq], wacc[kb][1]);
                }
            }
        }
    }

#pragma unroll
    for (int kb = 0; kb < 4; kb++) {
        if (kb < nb) {
            int k = kb * 64 + lane * 2;
            if (k < Lc)     atomicAdd(&sw[WC_OFF + k],     wacc[kb][0]);
            if (k + 1 < Lc) atomicAdd(&sw[WC_OFF + k + 1], wacc[kb][1]);
        }
    }
    __syncthreads();

    // ---- phase 3: S[c] = sum_k wc[k] * V[k][c] ----
    {
        const int c = tid & 15, part = tid >> 4;
        float acc = 0.f;
        for (int k = part; k < len; k += 16)
            acc = fmaf(sw[WC_OFF + k], sw[VS_OFF + k * 16 + c], acc);
        sw[SP_OFF + part * 16 + c] = acc;
    }
    __syncthreads();
    if (tid < 16) {
        float s = 0.f;
#pragma unroll
        for (int p = 0; p < 16; p++) s += sw[SP_OFF + p * 16 + tid];
        sw[SP_OFF + tid] = s;
    }
    __syncthreads();

    // ---- phase 4 (fused): out[b][e] += inv*(S_head . Wf[e, h*16:]) (+ bf on h==0) ----
    if (tid < 64) {
        float acc = 0.f;
        const float* wfr = Wf + tid * 64 + h * 16;
#pragma unroll
        for (int i = 0; i < 16; i++)
            acc = fmaf(sw[SP_OFF + i], wfr[i], acc);
        const float lenf = (float)len;
        const float invd = 1.0f / (lenf + 1e-8f);
        float val = acc * invd;
        if (h == 0) val = fmaf(bf[tid], lenf * invd, val);
        atomicAdd(out + b * 64 + tid, val);
    }
}

extern "C" void kernel_launch(void* const* d_in, const int* in_sizes, int n_in,
                              void* d_out, int out_size) {
    const float* input   = (const float*)d_in[0];
    const int*   mask    = (const int*)d_in[1];
    const float* pos_enc = (const float*)d_in[2];
    const float* Wk      = (const float*)d_in[3];
    const float* bk      = (const float*)d_in[4];
    const float* Wv      = (const float*)d_in[5];
    const float* bv      = (const float*)d_in[6];
    const float* Wq      = (const float*)d_in[7];
    const float* bq      = (const float*)d_in[8];
    const float* Wf      = (const float*)d_in[9];
    const float* bf      = (const float*)d_in[10];
    float* out           = (float*)d_out;

    len_kernel<<<Bc, 256>>>(mask, out);   // also zeroes out
    sort_kernel<<<1, 256>>>();

    const size_t smem1 = (size_t)SM1_F * sizeof(float);
    cudaFuncSetAttribute(attn_head_kernel,
                         cudaFuncAttributeMaxDynamicSharedMemorySize, (int)smem1);
    attn_head_kernel<<<Bc * 4, 256, smem1>>>(input, pos_enc,
                                             Wk, bk, Wv, bv, Wq, bq, Wf, bf, out);
}

// round 17
// speedup vs baseline: 1.2212x; 1.1803x over previous
#include <cuda_runtime.h>

constexpr int Bc = 512;
constexpr int Lc = 200;
constexpr int Ec = 64;

// ---------------- smem layout (floats) ----------------
constexpr int WTP    = 68;                        // wT[48][68]: wT[c][j]
constexpr int WT_OFF = 0;
constexpr int XSS    = 68;                        // xs[128][68] row-major
constexpr int XS_OFF = WT_OFF + 48 * WTP;         // 3264
constexpr int KTS    = 208;                       // kt[16][208]: kt[d][t]
constexpr int KT_OFF = XS_OFF + 128 * XSS;        // 11968
constexpr int QS_OFF = KT_OFF + 16 * KTS;         // q[200][16] (pre-scaled by 0.25*log2e)
constexpr int VS_OFF = QS_OFF + Lc * 16;          // v[200][16]
constexpr int WC_OFF = VS_OFF + Lc * 16;          // col sums [200]
constexpr int SP_OFF = WC_OFF + Lc + 8;           // partials [16][16]
constexpr int SM1_F  = SP_OFF + 256;              // 22160 floats = 88640 B

__device__ int g_len[Bc];
__device__ int g_order[Bc];

__device__ __forceinline__ float ex2f(float x) {
    float y;
    asm("ex2.approx.ftz.f32 %0, %1;" : "=f"(y) : "f"(x));
    return y;
}

// ---- pre-kernel 1: per-batch valid length + zero this batch's output slice ----
__global__ void len_kernel(const int* __restrict__ mask, float* __restrict__ out) {
    int b = blockIdx.x;
    int pred = (threadIdx.x < Lc) && (mask[(size_t)b * Lc + threadIdx.x] != 0);
    int len = __syncthreads_count(pred);
    if (threadIdx.x == 0) g_len[b] = len;
    if (threadIdx.x < Ec) out[b * Ec + threadIdx.x] = 0.0f;
}

// ---- pre-kernel 2: counting sort, descending len ----
__global__ void sort_kernel() {
    __shared__ int hist[Lc + 1];
    __shared__ int offs[Lc + 1];
    const int tid = threadIdx.x;
    for (int i = tid; i <= Lc; i += 256) hist[i] = 0;
    __syncthreads();
    for (int b = tid; b < Bc; b += 256) atomicAdd(&hist[g_len[b]], 1);
    __syncthreads();
    if (tid == 0) {
        int acc = 0;
        for (int l = Lc; l >= 0; l--) { offs[l] = acc; acc += hist[l]; }
    }
    __syncthreads();
    for (int b = tid; b < Bc; b += 256) {
        int pos = atomicAdd(&offs[g_len[b]], 1);
        g_order[pos] = b;
    }
}

extern __shared__ float sw[];

// phase-1 tile body: NR rows per thread (rows rowgrp + 32*rr), 6 cols
template <int NR>
__device__ __forceinline__ void proj_tile(int rowgrp, int colgrp, int tb, int len,
                                          const float* bias, float QSC) {
    float acc[NR][6];
#pragma unroll
    for (int rr = 0; rr < NR; rr++)
#pragma unroll
        for (int s = 0; s < 6; s++) acc[rr][s] = 0.f;

#pragma unroll
    for (int j4 = 0; j4 < 64; j4 += 4) {
        float4 xv[NR];
#pragma unroll
        for (int rr = 0; rr < NR; rr++)
            xv[rr] = *(const float4*)(sw + XS_OFF + (rowgrp + 32 * rr) * XSS + j4);
#pragma unroll
        for (int s = 0; s < 6; s++) {
            float4 wq = *(const float4*)(sw + WT_OFF + (colgrp + 8 * s) * WTP + j4);
#pragma unroll
            for (int rr = 0; rr < NR; rr++) {
                acc[rr][s] = fmaf(xv[rr].x, wq.x, acc[rr][s]);
                acc[rr][s] = fmaf(xv[rr].y, wq.y, acc[rr][s]);
                acc[rr][s] = fmaf(xv[rr].z, wq.z, acc[rr][s]);
                acc[rr][s] = fmaf(xv[rr].w, wq.w, acc[rr][s]);
            }
        }
    }

#pragma unroll
    for (int rr = 0; rr < NR; rr++) {
        int t = tb + rowgrp + 32 * rr;
        if (t < len) {
#pragma unroll
            for (int s = 0; s < 6; s++) {
                int c = colgrp + 8 * s;
                float v = acc[rr][s] + bias[s];
                if (c < 16)       sw[KT_OFF + c * KTS + t] = v;
                else if (c < 32)  sw[VS_OFF + t * 16 + (c - 16)] = v;
                else              sw[QS_OFF + t * 16 + (c - 32)] = v * QSC;
            }
        }
    }
}

__global__ void __launch_bounds__(256, 2)
attn_head_kernel(const float* __restrict__ input,
                 const float* __restrict__ pos_enc,
                 const float* __restrict__ Wk, const float* __restrict__ bk,
                 const float* __restrict__ Wv, const float* __restrict__ bv,
                 const float* __restrict__ Wq, const float* __restrict__ bq,
                 const float* __restrict__ Wf, const float* __restrict__ bf,
                 float* __restrict__ out) {
    const int tid  = threadIdx.x;
    const int lane = tid & 31;
    const int wid  = tid >> 5;
    const int b    = g_order[blockIdx.x >> 2];   // longest-first schedule
    const int h    = blockIdx.x & 3;
    const int len  = g_len[b];

    // ---- phase 0: weights transposed, vectorized: 3x LDG.128 + 3x STS.128 ----
    {
        const int i  = tid >> 4;          // 0..15 row within head slice
        const int j4 = (tid & 15) * 4;    // 0..60
        const int g  = (h * 16 + i) * 64 + j4;
        float4 vk = *(const float4*)(Wk + g);
        float4 vv = *(const float4*)(Wv + g);
        float4 vq = *(const float4*)(Wq + g);
        *(float4*)(sw + WT_OFF + (i)      * WTP + j4) = vk;
        *(float4*)(sw + WT_OFF + (16 + i) * WTP + j4) = vv;
        *(float4*)(sw + WT_OFF + (32 + i) * WTP + j4) = vq;
    }
    if (tid < Lc) sw[WC_OFF + tid] = 0.0f;
    __syncthreads();

    // ---- phase 1: register-tiled GEMM, len-adaptive row count ----
    const int rowgrp = tid >> 3;          // 0..31
    const int colgrp = tid & 7;           // 0..7
    const float QSC = 0.36067376022224085f;   // 0.25 * log2(e)

    float bias[6];
#pragma unroll
    for (int s = 0; s < 6; s++) {
        int c = colgrp + 8 * s, m = c >> 4, i = c & 15;
        bias[s] = (m == 0) ? bk[h * 16 + i] : ((m == 1) ? bv[h * 16 + i] : bq[h * 16 + i]);
    }

    const int ntiles = (len + 127) >> 7;
    for (int tile = 0; tile < ntiles; tile++) {
        const int tb = tile * 128;
        int R = len - tb; if (R > 128) R = 128;
        const int fmax = R << 4;
        const float4* in4 = (const float4*)(input + ((size_t)b * Lc + tb) * Ec);
        const float4* pe4 = (const float4*)(pos_enc + (size_t)tb * Ec);
#pragma unroll
        for (int v = 0; v < 8; v++) {
            int f = tid + v * 256;
            if (f < fmax) {
                int t = f >> 4, e0 = (f & 15) * 4;
                float4 a = in4[f], p = pe4[f];
                *(float4*)(sw + XS_OFF + t * XSS + e0) =
                    make_float4(a.x + p.x, a.y + p.y, a.z + p.z, a.w + p.w);
            }
        }
        __syncthreads();

        if (rowgrp < R) {
            const int nr = (R + 31) >> 5;
            switch (nr) {
                case 1: proj_tile<1>(rowgrp, colgrp, tb, len, bias, QSC); break;
                case 2: proj_tile<2>(rowgrp, colgrp, tb, len, bias, QSC); break;
                case 3: proj_tile<3>(rowgrp, colgrp, tb, len, bias, QSC); break;
                default: proj_tile<4>(rowgrp, colgrp, tb, len, bias, QSC); break;
            }
        }
        __syncthreads();
    }

    // ---- phase 2 (round-14 verbatim): scores + softmax + column sums ----
    // lane owns keys k = kb*64 + lane*2 + {0,1}; 4 query rows per warp iteration
    const int nb = (len + 63) >> 6;              // 1..4 k-blocks of 64
    float wacc[4][2];
#pragma unroll
    for (int kb = 0; kb < 4; kb++) { wacc[kb][0] = 0.f; wacc[kb][1] = 0.f; }

    for (int qb = wid * 4; qb < len; qb += 32) {
        float qv[4][16];
#pragma unroll
        for (int qq = 0; qq < 4; qq++) {
            int q = qb + qq; q = (q < len) ? q : 0;
            const float4* p = (const float4*)(sw + QS_OFF + q * 16);
#pragma unroll
            for (int jj = 0; jj < 4; jj++) {
                float4 v = p[jj];
                qv[qq][4 * jj + 0] = v.x; qv[qq][4 * jj + 1] = v.y;
                qv[qq][4 * jj + 2] = v.z; qv[qq][4 * jj + 3] = v.w;
            }
        }

        float ee[4][4][2];
        float z[4] = {0.f, 0.f, 0.f, 0.f};
#pragma unroll
        for (int kb = 0; kb < 4; kb++) {
            if (kb < nb) {
                const int k0 = kb * 64 + lane * 2;
                const float* kp = sw + KT_OFF + k0;
                float a0[4], a1[4];
#pragma unroll
                for (int qq = 0; qq < 4; qq++) { a0[qq] = 0.f; a1[qq] = 0.f; }
#pragma unroll
                for (int j = 0; j < 16; j++) {
                    float2 kt2 = *(const float2*)(kp + j * KTS);
#pragma unroll
                    for (int qq = 0; qq < 4; qq++) {
                        a0[qq] = fmaf(kt2.x, qv[qq][j], a0[qq]);
                        a1[qq] = fmaf(kt2.y, qv[qq][j], a1[qq]);
                    }
                }
                const bool ok0 = (k0 + 0) < len;
                const bool ok1 = (k0 + 1) < len;
#pragma unroll
                for (int qq = 0; qq < 4; qq++) {
                    float e0 = ok0 ? ex2f(a0[qq]) : 0.f;
                    float e1 = ok1 ? ex2f(a1[qq]) : 0.f;
                    ee[kb][qq][0] = e0; ee[kb][qq][1] = e1;
                    z[qq] += e0 + e1;
                }
            } else {
#pragma unroll
                for (int qq = 0; qq < 4; qq++) { ee[kb][qq][0] = 0.f; ee[kb][qq][1] = 0.f; }
            }
        }

#pragma unroll
        for (int o = 16; o; o >>= 1) {
            z[0] += __shfl_xor_sync(0xffffffffu, z[0], o);
            z[1] += __shfl_xor_sync(0xffffffffu, z[1], o);
            z[2] += __shfl_xor_sync(0xffffffffu, z[2], o);
            z[3] += __shfl_xor_sync(0xffffffffu, z[3], o);
        }
        float inv[4];
#pragma unroll
        for (int qq = 0; qq < 4; qq++)
            inv[qq] = (qb + qq < len) ? __fdividef(1.0f, z[qq]) : 0.0f;
#pragma unroll
        for (int kb = 0; kb < 4; kb++) {
            if (kb < nb) {
#pragma unroll
                for (int qq = 0; qq < 4; qq++) {
                    wacc[kb][0] = fmaf(ee[kb][qq][0], inv[qq], wacc[kb][0]);
                    wacc[kb][1] = fmaf(ee[kb][qq][1], inv[qq], wacc[kb][1]);
                }
            }
        }
    }

#pragma unroll
    for (int kb = 0; kb < 4; kb++) {
        if (kb < nb) {
            int k = kb * 64 + lane * 2;
            if (k < Lc)     atomicAdd(&sw[WC_OFF + k],     wacc[kb][0]);
            if (k + 1 < Lc) atomicAdd(&sw[WC_OFF + k + 1], wacc[kb][1]);
        }
    }
    __syncthreads();

    // ---- phase 3: S[c] = sum_k wc[k] * V[k][c] ----
    {
        const int c = tid & 15, part = tid >> 4;
        float acc = 0.f;
        for (int k = part; k < len; k += 16)
            acc = fmaf(sw[WC_OFF + k], sw[VS_OFF + k * 16 + c], acc);
        sw[SP_OFF + part * 16 + c] = acc;
    }
    __syncthreads();
    if (tid < 16) {
        float s = 0.f;
#pragma unroll
        for (int p = 0; p < 16; p++) s += sw[SP_OFF + p * 16 + tid];
        sw[SP_OFF + tid] = s;
    }
    __syncthreads();

    // ---- phase 4 (fused): out[b][e] += inv*(S_head . Wf[e, h*16:]) (+ bf on h==0) ----
    if (tid < 64) {
        float acc = 0.f;
        const float* wfr = Wf + tid * 64 + h * 16;
#pragma unroll
        for (int i = 0; i < 16; i++)
            acc = fmaf(sw[SP_OFF + i], wfr[i], acc);
        const float lenf = (float)len;
        const float invd = 1.0f / (lenf + 1e-8f);
        float val = acc * invd;
        if (h == 0) val = fmaf(bf[tid], lenf * invd, val);
        atomicAdd(out + b * 64 + tid, val);
    }
}

extern "C" void kernel_launch(void* const* d_in, const int* in_sizes, int n_in,
                              void* d_out, int out_size) {
    const float* input   = (const float*)d_in[0];
    const int*   mask    = (const int*)d_in[1];
    const float* pos_enc = (const float*)d_in[2];
    const float* Wk      = (const float*)d_in[3];
    const float* bk      = (const float*)d_in[4];
    const float* Wv      = (const float*)d_in[5];
    const float* bv      = (const float*)d_in[6];
    const float* Wq      = (const float*)d_in[7];
    const float* bq      = (const float*)d_in[8];
    const float* Wf      = (const float*)d_in[9];
    const float* bf      = (const float*)d_in[10];
    float* out           = (float*)d_out;

    len_kernel<<<Bc, 256>>>(mask, out);   // also zeroes out
    sort_kernel<<<1, 256>>>();

    const size_t smem1 = (size_t)SM1_F * sizeof(float);
    cudaFuncSetAttribute(attn_head_kernel,
                         cudaFuncAttributeMaxDynamicSharedMemorySize, (int)smem1);
    attn_head_kernel<<<Bc * 4, 256, smem1>>>(input, pos_enc,
                                             Wk, bk, Wv, bv, Wq, bq, Wf, bf, out);
}